// round 1
// baseline (speedup 1.0000x reference)
#include <cuda_runtime.h>
#include <math.h>

#define Sdim 2048
#define Edim 512
#define WIN  11
#define Bdim 8
#define Fdim (WIN * Edim)   // 5632
#define NTH  256

// Packed dual-fp32 FMA: a.{x,y} += {xlo,xhi} * w   (w broadcast to both lanes)
__device__ __forceinline__ void ffma2(float2& a, float xlo, float xhi, float w) {
    asm("{\n\t.reg .b64 X, Wd, A;\n\t"
        "mov.b64 X, {%2, %3};\n\t"
        "mov.b64 Wd, {%4, %4};\n\t"
        "mov.b64 A, {%0, %1};\n\t"
        "fma.rn.f32x2 A, X, Wd, A;\n\t"
        "mov.b64 {%0, %1}, A;\n\t}"
        : "+f"(a.x), "+f"(a.y)
        : "f"(xlo), "f"(xhi), "f"(w));
}

// Packed dual-fp32 FMA, both operands packed: a.x += xv.x*g.x ; a.y += xv.y*g.y
__device__ __forceinline__ void ffma2v(float2& a, float2 xv, float2 g) {
    asm("{\n\t.reg .b64 X, G, A;\n\t"
        "mov.b64 X, {%2, %3};\n\t"
        "mov.b64 G, {%4, %5};\n\t"
        "mov.b64 A, {%0, %1};\n\t"
        "fma.rn.f32x2 A, X, G, A;\n\t"
        "mov.b64 {%0, %1}, A;\n\t}"
        : "+f"(a.x), "+f"(a.y)
        : "f"(xv.x), "f"(xv.y), "f"(g.x), "f"(g.y));
}

extern __shared__ float smemf[];

// Layout of dynamic smem (floats):
//   xs2  : 4 planes * Fdim float2  = 45056 floats  (plane p holds (x[2p], x[2p+1]) pairs)
//   red  : 8 warps * 44 float2     = 704 floats
//   gbuf : 44 float2               = 88 floats
// total = 45848 floats = 183392 bytes

__global__ __launch_bounds__(NTH, 1)
void winattn_kernel(const float* __restrict__ x,
                    const float* __restrict__ W,
                    const float* __restrict__ bias,
                    float* __restrict__ out) {
    const int s   = blockIdx.x;
    const int tid = threadIdx.x;

    float2* xs2  = (float2*)smemf;                 // [4][Fdim]
    float2* red  = (float2*)(smemf + 4 * Fdim * 2); // [8][44]
    float2* gbuf = red + 8 * 44;                    // [44]

    // ---------------- Stage 1: fill smem planes with the x window ----------
    // 5632 quad-tasks: (p in 0..3) x (w in 0..10) x (equad in 0..127)
    #pragma unroll 4
    for (int k = 0; k < 22; k++) {
        int i   = tid + NTH * k;
        int p   = i / (WIN * 128);
        int rem = i - p * (WIN * 128);
        int w   = rem >> 7;
        int e   = (rem & 127) << 2;
        int row = s + w - 5;
        float4 x0 = make_float4(0.f, 0.f, 0.f, 0.f);
        float4 x1 = make_float4(0.f, 0.f, 0.f, 0.f);
        if ((unsigned)row < (unsigned)Sdim) {
            x0 = *(const float4*)(x + ((size_t)(2 * p)     * Sdim + row) * Edim + e);
            x1 = *(const float4*)(x + ((size_t)(2 * p + 1) * Sdim + row) * Edim + e);
        }
        float4 A  = make_float4(x0.x, x1.x, x0.y, x1.y);
        float4 Bq = make_float4(x0.z, x1.z, x0.w, x1.w);
        int f = w * Edim + e;                 // multiple of 4
        float4* dst = (float4*)xs2 + p * (Fdim / 2) + (f >> 1);
        dst[0] = A;
        dst[1] = Bq;
    }
    __syncthreads();

    // ---------------- Stage 2: gates GEMV, W streamed once -----------------
    float2 acc[4][WIN];
    #pragma unroll
    for (int p = 0; p < 4; p++)
        #pragma unroll
        for (int w = 0; w < WIN; w++)
            acc[p][w] = make_float2(0.f, 0.f);

    const float* Wrow = W + (size_t)s * (WIN * Fdim);

    #pragma unroll 2
    for (int it = 0; it < 11; it++) {
        int j  = tid + NTH * it;   // float-pair index; f0 = 2*j
        int f0 = 2 * j;

        float2 w2[WIN];
        #pragma unroll
        for (int w = 0; w < WIN; w++)
            w2[w] = *(const float2*)(Wrow + w * Fdim + f0);

        float4 xq[4];
        #pragma unroll
        for (int p = 0; p < 4; p++)
            xq[p] = ((const float4*)xs2)[p * (Fdim / 2) + j];

        #pragma unroll
        for (int w = 0; w < WIN; w++) {
            #pragma unroll
            for (int p = 0; p < 4; p++) {
                ffma2(acc[p][w], xq[p].x, xq[p].y, w2[w].x);
                ffma2(acc[p][w], xq[p].z, xq[p].w, w2[w].y);
            }
        }
    }

    // ---------------- Stage 3: reduce 256 partials -> 88 gates -------------
    #pragma unroll
    for (int off = 16; off > 0; off >>= 1) {
        #pragma unroll
        for (int p = 0; p < 4; p++)
            #pragma unroll
            for (int w = 0; w < WIN; w++) {
                acc[p][w].x += __shfl_xor_sync(0xffffffffu, acc[p][w].x, off);
                acc[p][w].y += __shfl_xor_sync(0xffffffffu, acc[p][w].y, off);
            }
    }
    int lane = tid & 31;
    int wrp  = tid >> 5;
    if (lane == 0) {
        #pragma unroll
        for (int p = 0; p < 4; p++)
            #pragma unroll
            for (int w = 0; w < WIN; w++)
                red[wrp * 44 + p * WIN + w] = acc[p][w];
    }
    __syncthreads();

    if (tid < 44) {
        float2 t = make_float2(0.f, 0.f);
        #pragma unroll
        for (int q = 0; q < 8; q++) {
            float2 v = red[q * 44 + tid];
            t.x += v.x;
            t.y += v.y;
        }
        int w = tid % WIN;
        float bb = bias[s * WIN + w];
        float2 g;
        g.x = 1.0f / (1.0f + expf(-(t.x + bb)));
        g.y = 1.0f / (1.0f + expf(-(t.y + bb)));
        gbuf[tid] = g;
    }
    __syncthreads();

    // ---------------- Stage 4: score + tanh, from smem ---------------------
    int p = tid >> 6;       // batch-pair
    int l = tid & 63;
    float2 gw[WIN];
    #pragma unroll
    for (int w = 0; w < WIN; w++)
        gw[w] = gbuf[p * WIN + w];

    #pragma unroll
    for (int k = 0; k < 8; k++) {
        int e = l + 64 * k;
        float2 a = make_float2(0.f, 0.f);
        #pragma unroll
        for (int w = 0; w < WIN; w++) {
            float2 xv = xs2[p * Fdim + w * Edim + e];
            ffma2v(a, xv, gw[w]);
        }
        out[(size_t)(2 * p)     * Sdim * Edim + (size_t)s * Edim + e] = tanhf(a.x);
        out[(size_t)(2 * p + 1) * Sdim * Edim + (size_t)s * Edim + e] = tanhf(a.y);
    }
}

extern "C" void kernel_launch(void* const* d_in, const int* in_sizes, int n_in,
                              void* d_out, int out_size) {
    const float* x  = (const float*)d_in[0];
    const float* W  = (const float*)d_in[1];
    const float* bv = (const float*)d_in[2];
    float* out = (float*)d_out;

    const int smem_bytes = (4 * Fdim * 2 + 8 * 44 * 2 + 44 * 2) * (int)sizeof(float); // 183392
    cudaFuncSetAttribute(winattn_kernel,
                         cudaFuncAttributeMaxDynamicSharedMemorySize, smem_bytes);

    winattn_kernel<<<Sdim, NTH, smem_bytes>>>(x, W, bv, out);
}

// round 2
// speedup vs baseline: 1.2167x; 1.2167x over previous
#include <cuda_runtime.h>
#include <math.h>

#define Sdim 2048
#define Edim 512
#define WIN  11
#define Fdim (WIN * Edim)   // 5632
#define NTH  512

// Packed dual-fp32 FMA: a.{x,y} += {xlo,xhi} * w   (w broadcast to both lanes)
__device__ __forceinline__ void ffma2(float2& a, float xlo, float xhi, float w) {
    asm("{\n\t.reg .b64 X, Wd, A;\n\t"
        "mov.b64 X, {%2, %3};\n\t"
        "mov.b64 Wd, {%4, %4};\n\t"
        "mov.b64 A, {%0, %1};\n\t"
        "fma.rn.f32x2 A, X, Wd, A;\n\t"
        "mov.b64 {%0, %1}, A;\n\t}"
        : "+f"(a.x), "+f"(a.y)
        : "f"(xlo), "f"(xhi), "f"(w));
}

// Packed dual-fp32 FMA, both operands packed: a.x += xv.x*g.x ; a.y += xv.y*g.y
__device__ __forceinline__ void ffma2v(float2& a, float2 xv, float2 g) {
    asm("{\n\t.reg .b64 X, G, A;\n\t"
        "mov.b64 X, {%2, %3};\n\t"
        "mov.b64 G, {%4, %5};\n\t"
        "mov.b64 A, {%0, %1};\n\t"
        "fma.rn.f32x2 A, X, G, A;\n\t"
        "mov.b64 {%0, %1}, A;\n\t}"
        : "+f"(a.x), "+f"(a.y)
        : "f"(xv.x), "f"(xv.y), "f"(g.x), "f"(g.y));
}

extern __shared__ float smemf[];

// Dynamic smem layout (floats):
//   xs2  : 4 planes * Fdim float2 = 45056 floats (plane p = batches 2p,2p+1 interleaved)
//   red  : 16 warps * 24 float2   = 768 floats
//   gbuf : 44 float2              = 88 floats
// total = 45912 floats = 183648 bytes

__global__ __launch_bounds__(NTH, 1)
void winattn_kernel(const float* __restrict__ x,
                    const float* __restrict__ W,
                    const float* __restrict__ bias,
                    float* __restrict__ out) {
    const int s   = blockIdx.x;
    const int tid = threadIdx.x;

    float2* xs2  = (float2*)smemf;                  // [4][Fdim]
    float2* red  = (float2*)(smemf + 4 * Fdim * 2); // [16][24]
    float2* gbuf = red + 16 * 24;                   // [44]

    // ---------------- Stage 1: fill smem planes with the x window ----------
    // 5632 quad-tasks: (p in 0..3) x (w in 0..10) x (equad in 0..127)
    #pragma unroll
    for (int k = 0; k < 11; k++) {
        int i   = tid + NTH * k;
        int p   = i / (WIN * 128);
        int rem = i - p * (WIN * 128);
        int w   = rem >> 7;
        int e   = (rem & 127) << 2;
        int row = s + w - 5;
        float4 x0 = make_float4(0.f, 0.f, 0.f, 0.f);
        float4 x1 = make_float4(0.f, 0.f, 0.f, 0.f);
        if ((unsigned)row < (unsigned)Sdim) {
            x0 = *(const float4*)(x + ((size_t)(2 * p)     * Sdim + row) * Edim + e);
            x1 = *(const float4*)(x + ((size_t)(2 * p + 1) * Sdim + row) * Edim + e);
        }
        float4 A  = make_float4(x0.x, x1.x, x0.y, x1.y);
        float4 Bq = make_float4(x0.z, x1.z, x0.w, x1.w);
        int f = w * Edim + e;                 // multiple of 4
        float4* dst = (float4*)xs2 + p * (Fdim / 2) + (f >> 1);
        dst[0] = A;
        dst[1] = Bq;
    }
    __syncthreads();

    // ---------------- Stage 2: gates GEMV, W streamed once -----------------
    // Group g=0 (threads 0..255) handles w = 0..5; g=1 (256..511) handles w = 6..10
    // (its 6th slot is a dummy clamped to a valid row, result discarded).
    const int g  = tid >> 8;
    const int h  = tid & 255;
    const int w0 = g * 6;

    float2 acc[4][6];
    #pragma unroll
    for (int p = 0; p < 4; p++)
        #pragma unroll
        for (int w = 0; w < 6; w++)
            acc[p][w] = make_float2(0.f, 0.f);

    const float* Wg = W + (size_t)s * (WIN * Fdim) + (size_t)w0 * Fdim;

    for (int it = 0; it < 6; it++) {
        int j4 = h + 256 * it;          // float4 index within a W row, < 1408
        if (j4 >= Fdim / 4) break;      // warp-uniform (boundary at h=128)
        int f0 = 4 * j4;

        float4 w4[6];
        #pragma unroll
        for (int w = 0; w < 6; w++) {
            int wr = (w0 + w < WIN) ? w : 4;   // clamp dummy row for group 1
            w4[w] = *(const float4*)(Wg + (size_t)wr * Fdim + f0);
        }

        float4 xa[4], xb[4];
        #pragma unroll
        for (int p = 0; p < 4; p++) {
            const float4* xp = (const float4*)(xs2 + p * Fdim);
            xa[p] = xp[2 * j4];
            xb[p] = xp[2 * j4 + 1];
        }

        #pragma unroll
        for (int w = 0; w < 6; w++) {
            #pragma unroll
            for (int p = 0; p < 4; p++) {
                ffma2(acc[p][w], xa[p].x, xa[p].y, w4[w].x);
                ffma2(acc[p][w], xa[p].z, xa[p].w, w4[w].y);
                ffma2(acc[p][w], xb[p].x, xb[p].y, w4[w].z);
                ffma2(acc[p][w], xb[p].z, xb[p].w, w4[w].w);
            }
        }
    }

    // ---------------- Stage 3: reduce partials -> 88 gates -----------------
    float* af = (float*)acc;            // 48 floats
    #pragma unroll
    for (int off = 16; off > 0; off >>= 1) {
        #pragma unroll
        for (int i = 0; i < 48; i++)
            af[i] += __shfl_xor_sync(0xffffffffu, af[i], off);
    }
    int lane = tid & 31;
    int wrp  = tid >> 5;                // 0..15 (group g owns warps g*8..g*8+7)
    if (lane == 0) {
        #pragma unroll
        for (int p = 0; p < 4; p++)
            #pragma unroll
            for (int w = 0; w < 6; w++)
                red[wrp * 24 + p * 6 + w] = acc[p][w];
    }
    __syncthreads();

    if (tid < 44) {
        int p = tid / WIN;
        int w = tid - p * WIN;
        int grp  = (w < 6) ? 0 : 1;
        int slot = p * 6 + (grp ? (w - 6) : w);
        float2 t = make_float2(0.f, 0.f);
        #pragma unroll
        for (int q = 0; q < 8; q++) {
            float2 v = red[(grp * 8 + q) * 24 + slot];
            t.x += v.x;
            t.y += v.y;
        }
        float bb = bias[s * WIN + w];
        float2 gg;
        gg.x = 1.0f / (1.0f + expf(-(t.x + bb)));
        gg.y = 1.0f / (1.0f + expf(-(t.y + bb)));
        gbuf[tid] = gg;                 // tid == p*WIN + w
    }
    __syncthreads();

    // ---------------- Stage 4: score + tanh, from smem ---------------------
    int p = tid >> 7;                   // batch-pair (128 threads each)
    int l = tid & 127;
    float2 gw[WIN];
    #pragma unroll
    for (int w = 0; w < WIN; w++)
        gw[w] = gbuf[p * WIN + w];

    #pragma unroll
    for (int k = 0; k < 4; k++) {
        int e = l + 128 * k;
        float2 a = make_float2(0.f, 0.f);
        #pragma unroll
        for (int w = 0; w < WIN; w++) {
            float2 xv = xs2[p * Fdim + w * Edim + e];
            ffma2v(a, xv, gw[w]);
        }
        out[(size_t)(2 * p)     * Sdim * Edim + (size_t)s * Edim + e] = tanhf(a.x);
        out[(size_t)(2 * p + 1) * Sdim * Edim + (size_t)s * Edim + e] = tanhf(a.y);
    }
}

extern "C" void kernel_launch(void* const* d_in, const int* in_sizes, int n_in,
                              void* d_out, int out_size) {
    const float* x  = (const float*)d_in[0];
    const float* W  = (const float*)d_in[1];
    const float* bv = (const float*)d_in[2];
    float* out = (float*)d_out;

    const int smem_bytes = (4 * Fdim * 2 + 16 * 24 * 2 + 44 * 2) * (int)sizeof(float); // 183648
    cudaFuncSetAttribute(winattn_kernel,
                         cudaFuncAttributeMaxDynamicSharedMemorySize, smem_bytes);

    winattn_kernel<<<Sdim, NTH, smem_bytes>>>(x, W, bv, out);
}